// round 5
// baseline (speedup 1.0000x reference)
#include <cuda_runtime.h>
#include <math.h>

#define NN 50000
#define EE 600000

// ------------------------- device scratch (no allocs allowed) ---------------
__device__ int   g_is64;
__device__ int2  g_edges[EE];
__device__ float g_hp [NN * 128];
__device__ float g_h  [NN * 128];
__device__ float g_acc[NN * 128];
__device__ float g_as [NN * 4];
__device__ float g_ad [NN * 4];
__device__ float g_m  [NN * 4];
__device__ float g_den[NN * 4];

// ------------------------- helpers ------------------------------------------
__device__ __forceinline__ float lrelu(float x) { return x > 0.f ? x : 0.2f * x; }

// branchless-ish float atomic max: int-max for >=0, uint-min for <0.
// (monotone mappings; mixed-sign cases are handled correctly because any
// positive beats any negative under both orderings used here)
__device__ __forceinline__ void atomicMaxF(float* a, float v) {
    if (v >= 0.f) atomicMax((int*)a, __float_as_int(v));
    else          atomicMin((unsigned int*)a, __float_as_uint(v));
}

__device__ __forceinline__ void redAdd4(float* p, float4 v) {
    asm volatile("red.global.add.v4.f32 [%0], {%1,%2,%3,%4};"
                 :: "l"(p), "f"(v.x), "f"(v.y), "f"(v.z), "f"(v.w) : "memory");
}
__device__ __forceinline__ void redAdd2(float* p, float2 v) {
    asm volatile("red.global.add.v2.f32 [%0], {%1,%2};"
                 :: "l"(p), "f"(v.x), "f"(v.y) : "memory");
}

// ------------------------- edge index dtype probe + convert ------------------
__global__ void probe_kernel(const unsigned long long* __restrict__ p) {
    if (threadIdx.x == 0 && blockIdx.x == 0) {
        int ok = 1;
        #pragma unroll
        for (int i = 0; i < 16; ++i)
            if (p[i] >= (unsigned long long)NN) ok = 0;
        g_is64 = ok;
    }
}

__global__ void convert_kernel(const void* __restrict__ ei, int E) {
    int e = blockIdx.x * blockDim.x + threadIdx.x;
    if (e >= E) return;
    int s, d;
    if (g_is64) {
        const long long* p = (const long long*)ei;
        s = (int)p[e]; d = (int)p[E + e];
    } else {
        const int* p = (const int*)ei;
        s = p[e]; d = p[E + e];
    }
    g_edges[e] = make_int2(s, d);
}

// ------------------------- GEMM N x 128 @ 128 x 128 --------------------------
// 64-row tile per 256-thread block; W(64KB)+X(32KB) in dynamic smem;
// 4x8 register microtile -> fp32-FMA-bound (~64 FMA/cyc/SM).
__global__ __launch_bounds__(256) void gemm128_kernel(
    const float* __restrict__ A, const float* __restrict__ W,
    float* __restrict__ C, int N)
{
    extern __shared__ float sm[];
    float* Ws = sm;            // 128*128
    float* Xs = sm + 16384;    // 64*128
    int tid  = threadIdx.x;
    int row0 = blockIdx.x * 64;

    const float4* Wv  = (const float4*)W;
    float4*       Wsv = (float4*)Ws;
    #pragma unroll 4
    for (int i = tid; i < 4096; i += 256) Wsv[i] = Wv[i];

    const float4* Av  = (const float4*)A;
    float4*       Xsv = (float4*)Xs;
    #pragma unroll 2
    for (int i = tid; i < 2048; i += 256) {
        int r = i >> 5;
        int gr = row0 + r;
        Xsv[i] = (gr < N) ? Av[gr * 32 + (i & 31)] : make_float4(0.f, 0.f, 0.f, 0.f);
    }
    __syncthreads();

    int tx = tid & 15, ty = tid >> 4;
    float acc[4][8];
    #pragma unroll
    for (int i = 0; i < 4; ++i)
        #pragma unroll
        for (int j = 0; j < 8; ++j) acc[i][j] = 0.f;

    const float* xbase = Xs + (ty * 4) * 128;
    const float* wbase = Ws + tx * 8;

    #pragma unroll 4
    for (int k = 0; k < 128; ++k) {
        float4 b0 = *(const float4*)(wbase + k * 128);
        float4 b1 = *(const float4*)(wbase + k * 128 + 4);
        #pragma unroll
        for (int i = 0; i < 4; ++i) {
            float a = xbase[i * 128 + k];
            acc[i][0] += a * b0.x; acc[i][1] += a * b0.y;
            acc[i][2] += a * b0.z; acc[i][3] += a * b0.w;
            acc[i][4] += a * b1.x; acc[i][5] += a * b1.y;
            acc[i][6] += a * b1.z; acc[i][7] += a * b1.w;
        }
    }

    #pragma unroll
    for (int i = 0; i < 4; ++i) {
        int r = row0 + ty * 4 + i;
        if (r < N) {
            float4* cp = (float4*)(C + r * 128 + tx * 8);
            cp[0] = make_float4(acc[i][0], acc[i][1], acc[i][2], acc[i][3]);
            cp[1] = make_float4(acc[i][4], acc[i][5], acc[i][6], acc[i][7]);
        }
    }
}

// ------------------------- attention scores + self-loop max seed (H=4,D=32) --
__global__ void scores4_kernel(const float* __restrict__ hp,
                               const float* __restrict__ att_s,
                               const float* __restrict__ att_d, int N)
{
    int idx = blockIdx.x * blockDim.x + threadIdx.x;
    if (idx >= N * 4) return;
    int n = idx >> 2, h = idx & 3;
    const float4* v = (const float4*)(hp + n * 128 + h * 32);
    const float4* a = (const float4*)(att_s + h * 32);
    const float4* b = (const float4*)(att_d + h * 32);
    float s = 0.f, d = 0.f;
    #pragma unroll
    for (int i = 0; i < 8; ++i) {
        float4 vv = v[i]; float4 aa = a[i]; float4 bb = b[i];
        s += vv.x * aa.x + vv.y * aa.y + vv.z * aa.z + vv.w * aa.w;
        d += vv.x * bb.x + vv.y * bb.y + vv.z * bb.z + vv.w * bb.w;
    }
    g_as[idx] = s;
    g_ad[idx] = d;
    g_m[idx]  = lrelu(s + d);   // self-loop logit seeds the segment max
}

// ------------------------- edge pass 1: segment max (H=4) --------------------
__global__ void edge_max4_kernel(int E) {
    int e = blockIdx.x * blockDim.x + threadIdx.x;
    if (e >= E) return;
    int2 sd = g_edges[e];
    float4 a = *(const float4*)(g_as + sd.x * 4);
    float4 b = *(const float4*)(g_ad + sd.y * 4);
    float* mp = g_m + sd.y * 4;
    atomicMaxF(mp + 0, lrelu(a.x + b.x));
    atomicMaxF(mp + 1, lrelu(a.y + b.y));
    atomicMaxF(mp + 2, lrelu(a.z + b.z));
    atomicMaxF(mp + 3, lrelu(a.w + b.w));
}

// ------------------------- node init: self-loop contribution (H=4) -----------
__global__ void node_init4_kernel(int N) {
    int idx = blockIdx.x * blockDim.x + threadIdx.x;
    if (idx >= N * 4) return;
    int n = idx >> 2, h = idx & 3;
    float al = lrelu(g_as[idx] + g_ad[idx]);
    float ex = __expf(al - g_m[idx]);
    g_den[idx] = ex;
    const float4* src = (const float4*)(g_hp + n * 128 + h * 32);
    float4*       dst = (float4*)(g_acc + n * 128 + h * 32);
    #pragma unroll
    for (int i = 0; i < 8; ++i) {
        float4 v = src[i];
        dst[i] = make_float4(ex * v.x, ex * v.y, ex * v.z, ex * v.w);
    }
}

// ------------------------- edge pass 2: fused denom + weighted scatter -------
// one warp per edge; lane l covers floats [4l,4l+4) of the 128-float row,
// head = l>>3.  denom and unnormalized sum accumulate together; the division
// happens node-parallel in the epilogue (saves a full 650MB edge pass).
__global__ void edge_agg4_kernel(int E) {
    int gt = blockIdx.x * blockDim.x + threadIdx.x;
    int e  = gt >> 5;
    if (e >= E) return;
    int lane = gt & 31;
    int2 sd  = g_edges[e];
    int h    = lane >> 3;
    float al = lrelu(__ldg(g_as + sd.x * 4 + h) + __ldg(g_ad + sd.y * 4 + h));
    float ex = __expf(al - __ldg(g_m + sd.y * 4 + h));
    if ((lane & 7) == 0) atomicAdd(g_den + sd.y * 4 + h, ex);
    float4 hv = *(const float4*)(g_hp + sd.x * 128 + lane * 4);
    redAdd4(g_acc + sd.y * 128 + lane * 4,
            make_float4(ex * hv.x, ex * hv.y, ex * hv.z, ex * hv.w));
}

// ------------------------- epilogue: /denom + bias + BN(eval) + ELU ----------
__global__ void epi4_kernel(const float* __restrict__ bias,
                            const float* __restrict__ gamma,
                            const float* __restrict__ beta,
                            float* __restrict__ out, int N)
{
    int i = blockIdx.x * blockDim.x + threadIdx.x;
    if (i >= N * 128) return;
    int n = i >> 7, k = i & 127, h = k >> 5;
    float v = g_acc[i] / (g_den[n * 4 + h] + 1e-16f) + bias[k];
    v = v * (gamma[k] * rsqrtf(1.f + 1e-5f)) + beta[k];
    out[i] = v > 0.f ? v : expm1f(v);
}

// ------------------------- layer 3 (H=1, D=CLS=10) ---------------------------
__global__ __launch_bounds__(320) void gemm10_kernel(
    const float* __restrict__ A, const float* __restrict__ W,
    float* __restrict__ C, int N)
{
    __shared__ float Xs[32 * 128];
    __shared__ float Ws[128 * 10];
    int tid  = threadIdx.x;          // 320
    int row0 = blockIdx.x * 32;
    for (int i = tid; i < 1280; i += 320) Ws[i] = W[i];
    for (int i = tid; i < 1024; i += 320) {
        int r = i >> 5;
        int gr = row0 + r;
        float4 v = make_float4(0.f, 0.f, 0.f, 0.f);
        if (gr < N) v = ((const float4*)A)[gr * 32 + (i & 31)];
        ((float4*)Xs)[i] = v;
    }
    __syncthreads();
    int r = tid / 10, c = tid - r * 10;
    if (r < 32) {
        int row = row0 + r;
        if (row < N) {
            float s = 0.f;
            #pragma unroll 8
            for (int k = 0; k < 128; ++k) s += Xs[r * 128 + k] * Ws[k * 10 + c];
            C[row * 10 + c] = s;
        }
    }
}

__global__ void scores1_kernel(const float* __restrict__ hp2,
                               const float* __restrict__ as2,
                               const float* __restrict__ ad2, int N)
{
    int n = blockIdx.x * blockDim.x + threadIdx.x;
    if (n >= N) return;
    float s = 0.f, d = 0.f;
    #pragma unroll
    for (int c = 0; c < 10; ++c) {
        float v = hp2[n * 10 + c];
        s += v * __ldg(as2 + c);
        d += v * __ldg(ad2 + c);
    }
    g_as[n] = s;
    g_ad[n] = d;
    g_m[n]  = lrelu(s + d);
}

__global__ void edge_max1_kernel(int E) {
    int e = blockIdx.x * blockDim.x + threadIdx.x;
    if (e >= E) return;
    int2 sd = g_edges[e];
    atomicMaxF(g_m + sd.y, lrelu(g_as[sd.x] + g_ad[sd.y]));
}

__global__ void node_init1_kernel(float* __restrict__ out, int N) {
    int n = blockIdx.x * blockDim.x + threadIdx.x;
    if (n >= N) return;
    float ex = __expf(lrelu(g_as[n] + g_ad[n]) - g_m[n]);
    g_den[n] = ex;
    #pragma unroll
    for (int c = 0; c < 10; ++c) out[n * 10 + c] = ex * g_hp[n * 10 + c];
}

__global__ void edge_agg1_kernel(float* __restrict__ out, int E) {
    int e = blockIdx.x * blockDim.x + threadIdx.x;
    if (e >= E) return;
    int2 sd = g_edges[e];
    float ex = __expf(lrelu(__ldg(g_as + sd.x) + __ldg(g_ad + sd.y)) - __ldg(g_m + sd.y));
    atomicAdd(g_den + sd.y, ex);
    const float2* src = (const float2*)(g_hp + sd.x * 10);  // 40B rows -> 8B aligned
    float* dst = out + sd.y * 10;
    #pragma unroll
    for (int i = 0; i < 5; ++i) {
        float2 v = src[i];
        redAdd2(dst + i * 2, make_float2(ex * v.x, ex * v.y));
    }
}

__global__ void epi1_kernel(float* __restrict__ out, const float* __restrict__ b2, int N) {
    int i = blockIdx.x * blockDim.x + threadIdx.x;
    if (i >= N * 10) return;
    int n = i / 10, c = i - n * 10;
    out[i] = out[i] / (g_den[n] + 1e-16f) + b2[c];
}

// ------------------------- host launch ---------------------------------------
extern "C" void kernel_launch(void* const* d_in, const int* in_sizes, int n_in,
                              void* d_out, int out_size)
{
    const float* x   = (const float*)d_in[0];
    const void*  ei  = d_in[1];
    const float* W0  = (const float*)d_in[2];
    const float* as0 = (const float*)d_in[3];
    const float* ad0 = (const float*)d_in[4];
    const float* b0  = (const float*)d_in[5];
    const float* g0  = (const float*)d_in[6];
    const float* be0 = (const float*)d_in[7];
    const float* W1  = (const float*)d_in[8];
    const float* as1 = (const float*)d_in[9];
    const float* ad1 = (const float*)d_in[10];
    const float* b1  = (const float*)d_in[11];
    const float* g1  = (const float*)d_in[12];
    const float* be1 = (const float*)d_in[13];
    const float* W2  = (const float*)d_in[14];
    const float* as2 = (const float*)d_in[15];
    const float* ad2 = (const float*)d_in[16];
    const float* b2  = (const float*)d_in[17];
    float* out = (float*)d_out;

    int N = in_sizes[0] / 128;
    int E = in_sizes[1] / 2;
    if (N > NN) N = NN;
    if (E > EE) E = EE;

    cudaFuncSetAttribute(gemm128_kernel,
                         cudaFuncAttributeMaxDynamicSharedMemorySize, 98304);

    float* hp_dev;  cudaGetSymbolAddress((void**)&hp_dev,  g_hp);
    float* h_dev;   cudaGetSymbolAddress((void**)&h_dev,   g_h);

    dim3 b256(256);
    int gbEdge  = (E + 255) / 256;
    int gbEdgeW = (E * 32 + 255) / 256;
    int gbNH    = (N * 4 + 255) / 256;
    int gbN     = (N + 255) / 256;
    int gbNF    = (N * 128 + 255) / 256;
    int gbG     = (N + 63) / 64;

    probe_kernel<<<1, 32>>>((const unsigned long long*)ei);
    convert_kernel<<<gbEdge, b256>>>(ei, E);

    // ---- layer 0 ----
    gemm128_kernel<<<gbG, b256, 98304>>>(x, W0, hp_dev, N);
    scores4_kernel<<<gbNH, b256>>>(hp_dev, as0, ad0, N);
    edge_max4_kernel<<<gbEdge, b256>>>(E);
    node_init4_kernel<<<gbNH, b256>>>(N);
    edge_agg4_kernel<<<gbEdgeW, b256>>>(E);
    epi4_kernel<<<gbNF, b256>>>(b0, g0, be0, h_dev, N);

    // ---- layer 1 ----
    gemm128_kernel<<<gbG, b256, 98304>>>(h_dev, W1, hp_dev, N);
    scores4_kernel<<<gbNH, b256>>>(hp_dev, as1, ad1, N);
    edge_max4_kernel<<<gbEdge, b256>>>(E);
    node_init4_kernel<<<gbNH, b256>>>(N);
    edge_agg4_kernel<<<gbEdgeW, b256>>>(E);
    epi4_kernel<<<gbNF, b256>>>(b1, g1, be1, h_dev, N);

    // ---- layer 2 (H=1, D=10) ----
    gemm10_kernel<<<(N + 31) / 32, 320>>>(h_dev, W2, hp_dev, N);
    scores1_kernel<<<gbN, b256>>>(hp_dev, as2, ad2, N);
    edge_max1_kernel<<<gbEdge, b256>>>(E);
    node_init1_kernel<<<gbN, b256>>>(out, N);
    edge_agg1_kernel<<<gbEdge, b256>>>(out, E);
    epi1_kernel<<<(N * 10 + 255) / 256, b256>>>(out, b2, N);
}

// round 6
// speedup vs baseline: 1.4139x; 1.4139x over previous
#include <cuda_runtime.h>
#include <mma.h>
#include <math.h>

using namespace nvcuda;

#define NN 50000
#define EE 600000

// ------------------------- device scratch (no allocs allowed) ---------------
__device__ int   g_is64;
__device__ int2  g_edges[EE];
__device__ int   g_col[EE];          // src ids sorted by dst (CSR)
__device__ int   g_deg[NN + 1];
__device__ int   g_off[NN + 1];
__device__ int   g_pos[NN];
__device__ float g_hp [NN * 128];
__device__ float g_h  [NN * 128];
__device__ float g_as [NN * 4];
__device__ float g_ad [NN * 4];

// ------------------------- helpers ------------------------------------------
__device__ __forceinline__ float lrelu(float x) { return x > 0.f ? x : 0.2f * x; }

// ------------------------- edge index dtype probe + convert ------------------
__global__ void probe_kernel(const unsigned long long* __restrict__ p) {
    if (threadIdx.x == 0 && blockIdx.x == 0) {
        int ok = 1;
        #pragma unroll
        for (int i = 0; i < 16; ++i)
            if (p[i] >= (unsigned long long)NN) ok = 0;
        g_is64 = ok;
    }
}

__global__ void convert_kernel(const void* __restrict__ ei, int E) {
    int e = blockIdx.x * blockDim.x + threadIdx.x;
    if (e >= E) return;
    int s, d;
    if (g_is64) {
        const long long* p = (const long long*)ei;
        s = (int)p[e]; d = (int)p[E + e];
    } else {
        const int* p = (const int*)ei;
        s = p[e]; d = p[E + e];
    }
    g_edges[e] = make_int2(s, d);
}

// ------------------------- CSR build (shared by all 3 layers) ----------------
__global__ void hist_kernel(int E) {
    int e = blockIdx.x * blockDim.x + threadIdx.x;
    if (e >= E) return;
    atomicAdd(&g_deg[g_edges[e].y], 1);
}

// single-block 2-level exclusive scan over g_deg[0..N) -> g_off, g_pos
__global__ __launch_bounds__(1024) void scan_kernel(int N) {
    __shared__ int ssum[1024];
    int t = threadIdx.x;
    int chunk = (N + 1023) / 1024;
    int b = t * chunk, e = min(b + chunk, N);
    int s = 0;
    for (int i = b; i < e; ++i) s += g_deg[i];
    ssum[t] = s;
    __syncthreads();
    // Hillis-Steele inclusive scan
    for (int off = 1; off < 1024; off <<= 1) {
        int v = (t >= off) ? ssum[t - off] : 0;
        __syncthreads();
        ssum[t] += v;
        __syncthreads();
    }
    int run = (t > 0) ? ssum[t - 1] : 0;   // exclusive
    for (int i = b; i < e; ++i) {
        int d = g_deg[i];
        g_off[i] = run;
        g_pos[i] = run;
        run += d;
    }
    if (t == 1023) g_off[N] = ssum[1023];
}

__global__ void scatter_kernel(int E) {
    int e = blockIdx.x * blockDim.x + threadIdx.x;
    if (e >= E) return;
    int2 sd = g_edges[e];
    int p = atomicAdd(&g_pos[sd.y], 1);
    g_col[p] = sd.x;
}

// ------------------------- GEMM N x 128 @ 128 x 128 (tf32 WMMA) --------------
// 64-row tile per 256-thread block (8 warps, each 32x32 via 2x2 m16n16k8).
// Epilogue: C tile staged in smem; attention scores a_s/a_d computed here,
// eliminating a separate 25MB-pass scores kernel.
__global__ __launch_bounds__(256) void gemm128_tf32_kernel(
    const float* __restrict__ A, const float* __restrict__ W,
    float* __restrict__ C,
    const float* __restrict__ att_s, const float* __restrict__ att_d,
    float* __restrict__ as_out, float* __restrict__ ad_out, int N)
{
    extern __shared__ float sm[];
    float* Ws = sm;            // 128*128 (64KB)
    float* Xs = sm + 16384;    // 64*128  (32KB)
    int tid  = threadIdx.x;
    int row0 = blockIdx.x * 64;

    const float4* Wv  = (const float4*)W;
    float4*       Wsv = (float4*)Ws;
    #pragma unroll 4
    for (int i = tid; i < 4096; i += 256) Wsv[i] = Wv[i];

    const float4* Av  = (const float4*)A;
    float4*       Xsv = (float4*)Xs;
    #pragma unroll 2
    for (int i = tid; i < 2048; i += 256) {
        int r = i >> 5;
        int gr = row0 + r;
        Xsv[i] = (gr < N) ? Av[gr * 32 + (i & 31)] : make_float4(0.f, 0.f, 0.f, 0.f);
    }
    __syncthreads();

    int warp = tid >> 5;
    int wr = warp >> 2;        // 0..1  (32-row band)
    int wc = warp & 3;         // 0..3  (32-col band)

    wmma::fragment<wmma::accumulator, 16, 16, 8, float> cf[2][2];
    #pragma unroll
    for (int i = 0; i < 2; ++i)
        #pragma unroll
        for (int j = 0; j < 2; ++j) wmma::fill_fragment(cf[i][j], 0.f);

    #pragma unroll
    for (int k = 0; k < 128; k += 8) {
        wmma::fragment<wmma::matrix_a, 16, 16, 8, wmma::precision::tf32, wmma::row_major> af[2];
        wmma::fragment<wmma::matrix_b, 16, 16, 8, wmma::precision::tf32, wmma::row_major> bf[2];
        #pragma unroll
        for (int i = 0; i < 2; ++i) {
            wmma::load_matrix_sync(af[i], Xs + (wr * 32 + i * 16) * 128 + k, 128);
            #pragma unroll
            for (int t = 0; t < af[i].num_elements; ++t)
                af[i].x[t] = wmma::__float_to_tf32(af[i].x[t]);
        }
        #pragma unroll
        for (int j = 0; j < 2; ++j) {
            wmma::load_matrix_sync(bf[j], Ws + k * 128 + wc * 32 + j * 16, 128);
            #pragma unroll
            for (int t = 0; t < bf[j].num_elements; ++t)
                bf[j].x[t] = wmma::__float_to_tf32(bf[j].x[t]);
        }
        #pragma unroll
        for (int i = 0; i < 2; ++i)
            #pragma unroll
            for (int j = 0; j < 2; ++j)
                wmma::mma_sync(cf[i][j], af[i], bf[j], cf[i][j]);
    }

    __syncthreads();                     // done reading Ws; reuse as C stage
    float* Cs = Ws;                      // 64*128
    #pragma unroll
    for (int i = 0; i < 2; ++i)
        #pragma unroll
        for (int j = 0; j < 2; ++j)
            wmma::store_matrix_sync(Cs + (wr * 32 + i * 16) * 128 + wc * 32 + j * 16,
                                    cf[i][j], 128, wmma::mem_row_major);
    __syncthreads();

    // write C to global
    const float4* Csv = (const float4*)Cs;
    #pragma unroll 2
    for (int i = tid; i < 2048; i += 256) {
        int r = i >> 5;
        int gr = row0 + r;
        if (gr < N) ((float4*)C)[gr * 32 + (i & 31)] = Csv[i];
    }
    // fused attention scores: thread -> (row, head)
    {
        int r = tid >> 2, h = tid & 3;
        int gr = row0 + r;
        if (gr < N) {
            const float* cp = Cs + r * 128 + h * 32;
            float s = 0.f, d = 0.f;
            #pragma unroll
            for (int j = 0; j < 32; ++j) {
                float v = cp[j];
                s += v * __ldg(att_s + h * 32 + j);
                d += v * __ldg(att_d + h * 32 + j);
            }
            as_out[gr * 4 + h] = s;
            ad_out[gr * 4 + h] = d;
        }
    }
}

// ------------------------- fused CSR aggregation, H=4, D=32 ------------------
// one warp per dst node; atomic-free. lane l owns features [4l,4l+4),
// head h = l>>3. phase1: strided segment-max; phase2: serial edges, all lanes
// on the same edge -> coalesced 512B hp gathers; denom identical per lane.
// epilogue (/denom + bias + BN + ELU) fused; output written once.
__global__ __launch_bounds__(256) void agg4_kernel(
    const float* __restrict__ bias, const float* __restrict__ gamma,
    const float* __restrict__ beta, float* __restrict__ outp, int N)
{
    int w = (blockIdx.x * blockDim.x + threadIdx.x) >> 5;
    if (w >= N) return;
    int lane = threadIdx.x & 31;
    int n = w;
    int beg = g_off[n], end = g_off[n + 1];

    float4 adn = *(const float4*)(g_ad + n * 4);
    float4 asn = *(const float4*)(g_as + n * 4);
    float4 sl4 = make_float4(lrelu(asn.x + adn.x), lrelu(asn.y + adn.y),
                             lrelu(asn.z + adn.z), lrelu(asn.w + adn.w));
    // ---- phase 1: per-head segment max (self-loop seeds) ----
    float4 mx = sl4;
    for (int e = beg + lane; e < end; e += 32) {
        int s = g_col[e];
        float4 a = *(const float4*)(g_as + s * 4);
        mx.x = fmaxf(mx.x, lrelu(a.x + adn.x));
        mx.y = fmaxf(mx.y, lrelu(a.y + adn.y));
        mx.z = fmaxf(mx.z, lrelu(a.z + adn.z));
        mx.w = fmaxf(mx.w, lrelu(a.w + adn.w));
    }
    #pragma unroll
    for (int o = 16; o > 0; o >>= 1) {
        mx.x = fmaxf(mx.x, __shfl_xor_sync(0xffffffffu, mx.x, o));
        mx.y = fmaxf(mx.y, __shfl_xor_sync(0xffffffffu, mx.y, o));
        mx.z = fmaxf(mx.z, __shfl_xor_sync(0xffffffffu, mx.z, o));
        mx.w = fmaxf(mx.w, __shfl_xor_sync(0xffffffffu, mx.w, o));
    }
    int h = lane >> 3;
    float mxh  = (h == 0) ? mx.x  : (h == 1) ? mx.y  : (h == 2) ? mx.z  : mx.w;
    float adnh = (h == 0) ? adn.x : (h == 1) ? adn.y : (h == 2) ? adn.z : adn.w;
    float slh  = (h == 0) ? sl4.x : (h == 1) ? sl4.y : (h == 2) ? sl4.z : sl4.w;

    // ---- phase 2: self-loop init + serial edge sweep ----
    int f = lane * 4;
    float exs = __expf(slh - mxh);
    float4 hv = *(const float4*)(g_hp + (size_t)n * 128 + f);
    float4 acc = make_float4(exs * hv.x, exs * hv.y, exs * hv.z, exs * hv.w);
    float den = exs;                     // identical across the 8 lanes/head
    #pragma unroll 4
    for (int e = beg; e < end; ++e) {
        int s = g_col[e];                // warp-uniform broadcast load
        float al = lrelu(__ldg(g_as + s * 4 + h) + adnh);
        float ex = __expf(al - mxh);
        den += ex;
        float4 v = *(const float4*)(g_hp + (size_t)s * 128 + f);
        acc.x += ex * v.x; acc.y += ex * v.y;
        acc.z += ex * v.z; acc.w += ex * v.w;
    }

    // ---- fused epilogue: /denom + bias + BN(eval) + ELU ----
    float inv = 1.f / (den + 1e-16f);
    const float bns = rsqrtf(1.f + 1e-5f);
    float4 bi = *(const float4*)(bias + f);
    float4 ga = *(const float4*)(gamma + f);
    float4 be = *(const float4*)(beta + f);
    float4 o;
    o.x = acc.x * inv + bi.x; o.x = o.x * (ga.x * bns) + be.x; o.x = o.x > 0.f ? o.x : expm1f(o.x);
    o.y = acc.y * inv + bi.y; o.y = o.y * (ga.y * bns) + be.y; o.y = o.y > 0.f ? o.y : expm1f(o.y);
    o.z = acc.z * inv + bi.z; o.z = o.z * (ga.z * bns) + be.z; o.z = o.z > 0.f ? o.z : expm1f(o.z);
    o.w = acc.w * inv + bi.w; o.w = o.w * (ga.w * bns) + be.w; o.w = o.w > 0.f ? o.w : expm1f(o.w);
    *(float4*)(outp + (size_t)n * 128 + f) = o;
}

// ------------------------- layer 3 (H=1, D=CLS=10) ---------------------------
__global__ __launch_bounds__(320) void gemm10_kernel(
    const float* __restrict__ A, const float* __restrict__ W,
    float* __restrict__ C, int N)
{
    __shared__ float Xs[32 * 128];
    __shared__ float Ws[128 * 10];
    int tid  = threadIdx.x;
    int row0 = blockIdx.x * 32;
    for (int i = tid; i < 1280; i += 320) Ws[i] = W[i];
    for (int i = tid; i < 1024; i += 320) {
        int r = i >> 5;
        int gr = row0 + r;
        float4 v = make_float4(0.f, 0.f, 0.f, 0.f);
        if (gr < N) v = ((const float4*)A)[gr * 32 + (i & 31)];
        ((float4*)Xs)[i] = v;
    }
    __syncthreads();
    int r = tid / 10, c = tid - r * 10;
    if (r < 32) {
        int row = row0 + r;
        if (row < N) {
            float s = 0.f;
            #pragma unroll 8
            for (int k = 0; k < 128; ++k) s += Xs[r * 128 + k] * Ws[k * 10 + c];
            C[row * 10 + c] = s;
        }
    }
}

__global__ void scores1_kernel(const float* __restrict__ hp2,
                               const float* __restrict__ as2,
                               const float* __restrict__ ad2, int N)
{
    int n = blockIdx.x * blockDim.x + threadIdx.x;
    if (n >= N) return;
    float s = 0.f, d = 0.f;
    #pragma unroll
    for (int c = 0; c < 10; ++c) {
        float v = hp2[n * 10 + c];
        s += v * __ldg(as2 + c);
        d += v * __ldg(ad2 + c);
    }
    g_as[n] = s;
    g_ad[n] = d;
}

// fused CSR aggregation for layer 2 (H=1, D=10), atomic-free
__global__ __launch_bounds__(256) void agg1_kernel(
    const float* __restrict__ b2, float* __restrict__ out, int N)
{
    int w = (blockIdx.x * blockDim.x + threadIdx.x) >> 5;
    if (w >= N) return;
    int lane = threadIdx.x & 31;
    int n = w;
    int beg = g_off[n], end = g_off[n + 1];
    float adn = g_ad[n];
    float sl  = lrelu(g_as[n] + adn);
    float mx  = sl;
    for (int e = beg + lane; e < end; e += 32)
        mx = fmaxf(mx, lrelu(g_as[g_col[e]] + adn));
    #pragma unroll
    for (int o = 16; o > 0; o >>= 1)
        mx = fmaxf(mx, __shfl_xor_sync(0xffffffffu, mx, o));

    float exs = __expf(sl - mx);
    float den = exs;
    float acc = (lane < 10) ? exs * g_hp[(size_t)n * 10 + lane] : 0.f;
    #pragma unroll 4
    for (int e = beg; e < end; ++e) {
        int s = g_col[e];
        float ex = __expf(lrelu(__ldg(g_as + s) + adn) - mx);
        den += ex;
        if (lane < 10) acc += ex * __ldg(g_hp + (size_t)s * 10 + lane);
    }
    if (lane < 10)
        out[(size_t)n * 10 + lane] = acc / (den + 1e-16f) + __ldg(b2 + lane);
}

// ------------------------- host launch ---------------------------------------
extern "C" void kernel_launch(void* const* d_in, const int* in_sizes, int n_in,
                              void* d_out, int out_size)
{
    const float* x   = (const float*)d_in[0];
    const void*  ei  = d_in[1];
    const float* W0  = (const float*)d_in[2];
    const float* as0 = (const float*)d_in[3];
    const float* ad0 = (const float*)d_in[4];
    const float* b0  = (const float*)d_in[5];
    const float* g0  = (const float*)d_in[6];
    const float* be0 = (const float*)d_in[7];
    const float* W1  = (const float*)d_in[8];
    const float* as1 = (const float*)d_in[9];
    const float* ad1 = (const float*)d_in[10];
    const float* b1  = (const float*)d_in[11];
    const float* g1  = (const float*)d_in[12];
    const float* be1 = (const float*)d_in[13];
    const float* W2  = (const float*)d_in[14];
    const float* as2 = (const float*)d_in[15];
    const float* ad2 = (const float*)d_in[16];
    const float* b2  = (const float*)d_in[17];
    float* out = (float*)d_out;

    int N = in_sizes[0] / 128;
    int E = in_sizes[1] / 2;
    if (N > NN) N = NN;
    if (E > EE) E = EE;

    cudaFuncSetAttribute(gemm128_tf32_kernel,
                         cudaFuncAttributeMaxDynamicSharedMemorySize, 98304);

    float* hp_dev;  cudaGetSymbolAddress((void**)&hp_dev,  g_hp);
    float* h_dev;   cudaGetSymbolAddress((void**)&h_dev,   g_h);
    float* as_dev;  cudaGetSymbolAddress((void**)&as_dev,  g_as);
    float* ad_dev;  cudaGetSymbolAddress((void**)&ad_dev,  g_ad);
    int*   deg_dev; cudaGetSymbolAddress((void**)&deg_dev, g_deg);

    dim3 b256(256);
    int gbEdge = (E + 255) / 256;
    int gbN    = (N + 255) / 256;
    int gbG    = (N + 63) / 64;
    int gbWarp = (N * 32 + 255) / 256;   // one warp per node

    // ---- edge preprocessing + CSR build (shared by all 3 layers) ----
    probe_kernel<<<1, 32>>>((const unsigned long long*)ei);
    convert_kernel<<<gbEdge, b256>>>(ei, E);
    cudaMemsetAsync(deg_dev, 0, (NN + 1) * sizeof(int));
    hist_kernel<<<gbEdge, b256>>>(E);
    scan_kernel<<<1, 1024>>>(N);
    scatter_kernel<<<gbEdge, b256>>>(E);

    // ---- layer 0 ----
    gemm128_tf32_kernel<<<gbG, b256, 98304>>>(x, W0, hp_dev, as0, ad0, as_dev, ad_dev, N);
    agg4_kernel<<<gbWarp, b256>>>(b0, g0, be0, h_dev, N);

    // ---- layer 1 ----
    gemm128_tf32_kernel<<<gbG, b256, 98304>>>(h_dev, W1, hp_dev, as1, ad1, as_dev, ad_dev, N);
    agg4_kernel<<<gbWarp, b256>>>(b1, g1, be1, h_dev, N);

    // ---- layer 2 (H=1, D=10) ----
    gemm10_kernel<<<(N + 31) / 32, 320>>>(h_dev, W2, hp_dev, N);
    scores1_kernel<<<gbN, b256>>>(hp_dev, as2, ad2, N);
    agg1_kernel<<<gbWarp, b256>>>(b2, out, N);
}

// round 8
// speedup vs baseline: 1.7384x; 1.2295x over previous
#include <cuda_runtime.h>
#include <mma.h>
#include <math.h>

using namespace nvcuda;

#define NN 50000
#define EE 600000
#define SCAN_B 256
#define SCAN_NBLK ((NN + SCAN_B - 1) / SCAN_B)   // 196

// ------------------------- device scratch (no allocs allowed) ---------------
__device__ int   g_is64;
__device__ int2  g_edges[EE];
__device__ int   g_col[EE];          // src ids sorted by dst (CSR)
__device__ int   g_deg[NN + 1];
__device__ int   g_off[NN + 1];
__device__ int   g_pos[NN];
__device__ int   g_bsum[SCAN_B];
__device__ float g_hp [NN * 128];
__device__ float g_h  [NN * 128];
__device__ float g_as [NN * 4];
__device__ float g_ad [NN * 4];

// ------------------------- helpers ------------------------------------------
__device__ __forceinline__ float lrelu(float x) { return x > 0.f ? x : 0.2f * x; }

// ------------------------- edge index dtype probe ----------------------------
__global__ void probe_kernel(const unsigned long long* __restrict__ p) {
    if (threadIdx.x == 0 && blockIdx.x == 0) {
        int ok = 1;
        #pragma unroll
        for (int i = 0; i < 16; ++i)
            if (p[i] >= (unsigned long long)NN) ok = 0;
        g_is64 = ok;
    }
}

// fused: dtype convert to int2 + dst-degree histogram (one edge pass)
__global__ void convert_hist_kernel(const void* __restrict__ ei, int E) {
    int e = blockIdx.x * blockDim.x + threadIdx.x;
    if (e >= E) return;
    int s, d;
    if (g_is64) {
        const long long* p = (const long long*)ei;
        s = (int)p[e]; d = (int)p[E + e];
    } else {
        const int* p = (const int*)ei;
        s = p[e]; d = p[E + e];
    }
    g_edges[e] = make_int2(s, d);
    atomicAdd(&g_deg[d], 1);
}

// ------------------------- CSR build: 3-stage multi-block scan ---------------
__global__ __launch_bounds__(SCAN_B) void scanA_kernel(int N) {
    __shared__ int sm[SCAN_B];
    int i = blockIdx.x * SCAN_B + threadIdx.x;
    int t = threadIdx.x;
    sm[t] = (i < N) ? g_deg[i] : 0;
    __syncthreads();
    #pragma unroll
    for (int o = SCAN_B / 2; o > 0; o >>= 1) {
        if (t < o) sm[t] += sm[t + o];
        __syncthreads();
    }
    if (t == 0) g_bsum[blockIdx.x] = sm[0];
}

__global__ __launch_bounds__(SCAN_B) void scanB_kernel(int nb) {
    __shared__ int sm[SCAN_B];
    int t = threadIdx.x;
    int v = (t < nb) ? g_bsum[t] : 0;
    sm[t] = v;
    __syncthreads();
    #pragma unroll
    for (int o = 1; o < SCAN_B; o <<= 1) {
        int u = (t >= o) ? sm[t - o] : 0;
        __syncthreads();
        sm[t] += u;
        __syncthreads();
    }
    g_bsum[t] = sm[t] - v;     // exclusive
}

__global__ __launch_bounds__(SCAN_B) void scanC_kernel(int N) {
    __shared__ int sm[SCAN_B];
    int i = blockIdx.x * SCAN_B + threadIdx.x;
    int t = threadIdx.x;
    int v = (i < N) ? g_deg[i] : 0;
    sm[t] = v;
    __syncthreads();
    #pragma unroll
    for (int o = 1; o < SCAN_B; o <<= 1) {
        int u = (t >= o) ? sm[t - o] : 0;
        __syncthreads();
        sm[t] += u;
        __syncthreads();
    }
    int excl = sm[t] - v + g_bsum[blockIdx.x];
    if (i < N) { g_off[i] = excl; g_pos[i] = excl; }
    if (i == N - 1) g_off[N] = excl + v;
}

__global__ void scatter_kernel(int E) {
    int e = blockIdx.x * blockDim.x + threadIdx.x;
    if (e >= E) return;
    int2 sd = g_edges[e];
    int p = atomicAdd(&g_pos[sd.y], 1);
    g_col[p] = sd.x;
}

// ------------------------- GEMM N x 128 @ 128 x 128 (tf32 WMMA) --------------
// 64-row tile per 256-thread block (8 warps, each 32x32 via 2x2 m16n16k8).
// Epilogue: C staged in smem; attention scores a_s/a_d fused here.
__global__ __launch_bounds__(256) void gemm128_tf32_kernel(
    const float* __restrict__ A, const float* __restrict__ W,
    float* __restrict__ C,
    const float* __restrict__ att_s, const float* __restrict__ att_d,
    float* __restrict__ as_out, float* __restrict__ ad_out, int N)
{
    extern __shared__ float sm[];
    float* Ws = sm;            // 128*128 (64KB)
    float* Xs = sm + 16384;    // 64*128  (32KB)
    int tid  = threadIdx.x;
    int row0 = blockIdx.x * 64;

    const float4* Wv  = (const float4*)W;
    float4*       Wsv = (float4*)Ws;
    #pragma unroll 4
    for (int i = tid; i < 4096; i += 256) Wsv[i] = Wv[i];

    const float4* Av  = (const float4*)A;
    float4*       Xsv = (float4*)Xs;
    #pragma unroll 2
    for (int i = tid; i < 2048; i += 256) {
        int r = i >> 5;
        int gr = row0 + r;
        Xsv[i] = (gr < N) ? Av[gr * 32 + (i & 31)] : make_float4(0.f, 0.f, 0.f, 0.f);
    }
    __syncthreads();

    int warp = tid >> 5;
    int wr = warp >> 2;        // 0..1  (32-row band)
    int wc = warp & 3;         // 0..3  (32-col band)

    wmma::fragment<wmma::accumulator, 16, 16, 8, float> cf[2][2];
    #pragma unroll
    for (int i = 0; i < 2; ++i)
        #pragma unroll
        for (int j = 0; j < 2; ++j) wmma::fill_fragment(cf[i][j], 0.f);

    #pragma unroll
    for (int k = 0; k < 128; k += 8) {
        wmma::fragment<wmma::matrix_a, 16, 16, 8, wmma::precision::tf32, wmma::row_major> af[2];
        wmma::fragment<wmma::matrix_b, 16, 16, 8, wmma::precision::tf32, wmma::row_major> bf[2];
        #pragma unroll
        for (int i = 0; i < 2; ++i) {
            wmma::load_matrix_sync(af[i], Xs + (wr * 32 + i * 16) * 128 + k, 128);
            #pragma unroll
            for (int t = 0; t < af[i].num_elements; ++t)
                af[i].x[t] = wmma::__float_to_tf32(af[i].x[t]);
        }
        #pragma unroll
        for (int j = 0; j < 2; ++j) {
            wmma::load_matrix_sync(bf[j], Ws + k * 128 + wc * 32 + j * 16, 128);
            #pragma unroll
            for (int t = 0; t < bf[j].num_elements; ++t)
                bf[j].x[t] = wmma::__float_to_tf32(bf[j].x[t]);
        }
        #pragma unroll
        for (int i = 0; i < 2; ++i)
            #pragma unroll
            for (int j = 0; j < 2; ++j)
                wmma::mma_sync(cf[i][j], af[i], bf[j], cf[i][j]);
    }

    __syncthreads();                     // done reading Ws; reuse as C stage
    float* Cs = Ws;                      // 64*128
    #pragma unroll
    for (int i = 0; i < 2; ++i)
        #pragma unroll
        for (int j = 0; j < 2; ++j)
            wmma::store_matrix_sync(Cs + (wr * 32 + i * 16) * 128 + wc * 32 + j * 16,
                                    cf[i][j], 128, wmma::mem_row_major);
    __syncthreads();

    // write C to global
    const float4* Csv = (const float4*)Cs;
    #pragma unroll 2
    for (int i = tid; i < 2048; i += 256) {
        int r = i >> 5;
        int gr = row0 + r;
        if (gr < N) ((float4*)C)[gr * 32 + (i & 31)] = Csv[i];
    }
    // fused attention scores: thread -> (row, head)
    {
        int r = tid >> 2, h = tid & 3;
        int gr = row0 + r;
        if (gr < N) {
            const float* cp = Cs + r * 128 + h * 32;
            float s = 0.f, d = 0.f;
            #pragma unroll
            for (int j = 0; j < 32; ++j) {
                float v = cp[j];
                s += v * __ldg(att_s + h * 32 + j);
                d += v * __ldg(att_d + h * 32 + j);
            }
            as_out[gr * 4 + h] = s;
            ad_out[gr * 4 + h] = d;
        }
    }
}

// ------------------------- fused CSR aggregation, H=4, D=32 ------------------
// one warp per dst node; atomic-free; col prefetch pipelines the e->col->{as,hp}
// indirection chain.
__global__ __launch_bounds__(256) void agg4_kernel(
    const float* __restrict__ bias, const float* __restrict__ gamma,
    const float* __restrict__ beta, float* __restrict__ outp, int N)
{
    int w = (blockIdx.x * blockDim.x + threadIdx.x) >> 5;
    if (w >= N) return;
    int lane = threadIdx.x & 31;
    int n = w;
    int beg = g_off[n], end = g_off[n + 1];

    float4 adn = *(const float4*)(g_ad + n * 4);
    float4 asn = *(const float4*)(g_as + n * 4);
    float4 sl4 = make_float4(lrelu(asn.x + adn.x), lrelu(asn.y + adn.y),
                             lrelu(asn.z + adn.z), lrelu(asn.w + adn.w));
    // ---- phase 1: per-head segment max (self-loop seeds) ----
    float4 mx = sl4;
    for (int e = beg + lane; e < end; e += 32) {
        int s = g_col[e];
        float4 a = *(const float4*)(g_as + s * 4);
        mx.x = fmaxf(mx.x, lrelu(a.x + adn.x));
        mx.y = fmaxf(mx.y, lrelu(a.y + adn.y));
        mx.z = fmaxf(mx.z, lrelu(a.z + adn.z));
        mx.w = fmaxf(mx.w, lrelu(a.w + adn.w));
    }
    #pragma unroll
    for (int o = 16; o > 0; o >>= 1) {
        mx.x = fmaxf(mx.x, __shfl_xor_sync(0xffffffffu, mx.x, o));
        mx.y = fmaxf(mx.y, __shfl_xor_sync(0xffffffffu, mx.y, o));
        mx.z = fmaxf(mx.z, __shfl_xor_sync(0xffffffffu, mx.z, o));
        mx.w = fmaxf(mx.w, __shfl_xor_sync(0xffffffffu, mx.w, o));
    }
    int h = lane >> 3;
    float mxh  = (h == 0) ? mx.x  : (h == 1) ? mx.y  : (h == 2) ? mx.z  : mx.w;
    float adnh = (h == 0) ? adn.x : (h == 1) ? adn.y : (h == 2) ? adn.z : adn.w;
    float slh  = (h == 0) ? sl4.x : (h == 1) ? sl4.y : (h == 2) ? sl4.z : sl4.w;

    // ---- phase 2: self-loop init + pipelined serial edge sweep ----
    int f = lane * 4;
    float exs = __expf(slh - mxh);
    float4 hv = *(const float4*)(g_hp + (size_t)n * 128 + f);
    float4 acc = make_float4(exs * hv.x, exs * hv.y, exs * hv.z, exs * hv.w);
    float den = exs;                     // identical across the 8 lanes/head
    int sN = (beg < end) ? g_col[beg] : 0;
    #pragma unroll 4
    for (int e = beg; e < end; ++e) {
        int s = sN;
        sN = (e + 1 < end) ? g_col[e + 1] : 0;   // prefetch next col id
        float al = lrelu(__ldg(g_as + s * 4 + h) + adnh);
        float ex = __expf(al - mxh);
        den += ex;
        float4 v = *(const float4*)(g_hp + (size_t)s * 128 + f);
        acc.x += ex * v.x; acc.y += ex * v.y;
        acc.z += ex * v.z; acc.w += ex * v.w;
    }

    // ---- fused epilogue: /denom + bias + BN(eval) + ELU ----
    float inv = 1.f / (den + 1e-16f);
    const float bns = rsqrtf(1.f + 1e-5f);
    float4 bi = *(const float4*)(bias + f);
    float4 ga = *(const float4*)(gamma + f);
    float4 be = *(const float4*)(beta + f);
    float4 o;
    o.x = acc.x * inv + bi.x; o.x = o.x * (ga.x * bns) + be.x; o.x = o.x > 0.f ? o.x : expm1f(o.x);
    o.y = acc.y * inv + bi.y; o.y = o.y * (ga.y * bns) + be.y; o.y = o.y > 0.f ? o.y : expm1f(o.y);
    o.z = acc.z * inv + bi.z; o.z = o.z * (ga.z * bns) + be.z; o.z = o.z > 0.f ? o.z : expm1f(o.z);
    o.w = acc.w * inv + bi.w; o.w = o.w * (ga.w * bns) + be.w; o.w = o.w > 0.f ? o.w : expm1f(o.w);
    *(float4*)(outp + (size_t)n * 128 + f) = o;
}

// ------------------------- layer 3 (H=1, D=CLS=10) ---------------------------
__global__ __launch_bounds__(320) void gemm10_kernel(
    const float* __restrict__ A, const float* __restrict__ W,
    float* __restrict__ C, int N)
{
    __shared__ float Xs[32 * 128];
    __shared__ float Ws[128 * 10];
    int tid  = threadIdx.x;
    int row0 = blockIdx.x * 32;
    for (int i = tid; i < 1280; i += 320) Ws[i] = W[i];
    for (int i = tid; i < 1024; i += 320) {
        int r = i >> 5;
        int gr = row0 + r;
        float4 v = make_float4(0.f, 0.f, 0.f, 0.f);
        if (gr < N) v = ((const float4*)A)[gr * 32 + (i & 31)];
        ((float4*)Xs)[i] = v;
    }
    __syncthreads();
    int r = tid / 10, c = tid - r * 10;
    if (r < 32) {
        int row = row0 + r;
        if (row < N) {
            float s = 0.f;
            #pragma unroll 8
            for (int k = 0; k < 128; ++k) s += Xs[r * 128 + k] * Ws[k * 10 + c];
            C[row * 10 + c] = s;
        }
    }
}

__global__ void scores1_kernel(const float* __restrict__ hp2,
                               const float* __restrict__ as2,
                               const float* __restrict__ ad2, int N)
{
    int n = blockIdx.x * blockDim.x + threadIdx.x;
    if (n >= N) return;
    float s = 0.f, d = 0.f;
    #pragma unroll
    for (int c = 0; c < 10; ++c) {
        float v = hp2[n * 10 + c];
        s += v * __ldg(as2 + c);
        d += v * __ldg(ad2 + c);
    }
    g_as[n] = s;
    g_ad[n] = d;
}

// fused CSR aggregation for layer 2 (H=1, D=10), atomic-free
__global__ __launch_bounds__(256) void agg1_kernel(
    const float* __restrict__ b2, float* __restrict__ out, int N)
{
    int w = (blockIdx.x * blockDim.x + threadIdx.x) >> 5;
    if (w >= N) return;
    int lane = threadIdx.x & 31;
    int n = w;
    int beg = g_off[n], end = g_off[n + 1];
    float adn = g_ad[n];
    float sl  = lrelu(g_as[n] + adn);
    float mx  = sl;
    for (int e = beg + lane; e < end; e += 32)
        mx = fmaxf(mx, lrelu(g_as[g_col[e]] + adn));
    #pragma unroll
    for (int o = 16; o > 0; o >>= 1)
        mx = fmaxf(mx, __shfl_xor_sync(0xffffffffu, mx, o));

    float exs = __expf(sl - mx);
    float den = exs;
    float acc = (lane < 10) ? exs * g_hp[(size_t)n * 10 + lane] : 0.f;
    int sN = (beg < end) ? g_col[beg] : 0;
    #pragma unroll 4
    for (int e = beg; e < end; ++e) {
        int s = sN;
        sN = (e + 1 < end) ? g_col[e + 1] : 0;
        float ex = __expf(lrelu(__ldg(g_as + s) + adn) - mx);
        den += ex;
        if (lane < 10) acc += ex * __ldg(g_hp + (size_t)s * 10 + lane);
    }
    if (lane < 10)
        out[(size_t)n * 10 + lane] = acc / (den + 1e-16f) + __ldg(b2 + lane);
}

// ------------------------- host launch ---------------------------------------
extern "C" void kernel_launch(void* const* d_in, const int* in_sizes, int n_in,
                              void* d_out, int out_size)
{
    const float* x   = (const float*)d_in[0];
    const void*  ei  = d_in[1];
    const float* W0  = (const float*)d_in[2];
    const float* as0 = (const float*)d_in[3];
    const float* ad0 = (const float*)d_in[4];
    const float* b0  = (const float*)d_in[5];
    const float* g0  = (const float*)d_in[6];
    const float* be0 = (const float*)d_in[7];
    const float* W1  = (const float*)d_in[8];
    const float* as1 = (const float*)d_in[9];
    const float* ad1 = (const float*)d_in[10];
    const float* b1  = (const float*)d_in[11];
    const float* g1  = (const float*)d_in[12];
    const float* be1 = (const float*)d_in[13];
    const float* W2  = (const float*)d_in[14];
    const float* as2 = (const float*)d_in[15];
    const float* ad2 = (const float*)d_in[16];
    const float* b2  = (const float*)d_in[17];
    float* out = (float*)d_out;

    int N = in_sizes[0] / 128;
    int E = in_sizes[1] / 2;
    if (N > NN) N = NN;
    if (E > EE) E = EE;

    cudaFuncSetAttribute(gemm128_tf32_kernel,
                         cudaFuncAttributeMaxDynamicSharedMemorySize, 98304);

    float* hp_dev;  cudaGetSymbolAddress((void**)&hp_dev,  g_hp);
    float* h_dev;   cudaGetSymbolAddress((void**)&h_dev,   g_h);
    float* as_dev;  cudaGetSymbolAddress((void**)&as_dev,  g_as);
    float* ad_dev;  cudaGetSymbolAddress((void**)&ad_dev,  g_ad);
    int*   deg_dev; cudaGetSymbolAddress((void**)&deg_dev, g_deg);

    dim3 b256(256);
    int gbEdge = (E + 255) / 256;
    int gbN    = (N + 255) / 256;
    int gbG    = (N + 63) / 64;
    int gbWarp = (N * 32 + 255) / 256;   // one warp per node
    int nScanB = (N + SCAN_B - 1) / SCAN_B;

    // ---- edge preprocessing + CSR build (shared by all 3 layers) ----
    probe_kernel<<<1, 32>>>((const unsigned long long*)ei);
    cudaMemsetAsync(deg_dev, 0, (NN + 1) * sizeof(int));
    convert_hist_kernel<<<gbEdge, b256>>>(ei, E);
    scanA_kernel<<<nScanB, SCAN_B>>>(N);
    scanB_kernel<<<1, SCAN_B>>>(nScanB);
    scanC_kernel<<<nScanB, SCAN_B>>>(N);
    scatter_kernel<<<gbEdge, b256>>>(E);

    // ---- layer 0 ----
    gemm128_tf32_kernel<<<gbG, b256, 98304>>>(x, W0, hp_dev, as0, ad0, as_dev, ad_dev, N);
    agg4_kernel<<<gbWarp, b256>>>(b0, g0, be0, h_dev, N);

    // ---- layer 1 ----
    gemm128_tf32_kernel<<<gbG, b256, 98304>>>(h_dev, W1, hp_dev, as1, ad1, as_dev, ad_dev, N);
    agg4_kernel<<<gbWarp, b256>>>(b1, g1, be1, h_dev, N);

    // ---- layer 2 (H=1, D=10) ----
    gemm10_kernel<<<(N + 31) / 32, 320>>>(h_dev, W2, hp_dev, N);
    scores1_kernel<<<gbN, b256>>>(hp_dev, as2, ad2, N);
    agg1_kernel<<<gbWarp, b256>>>(b2, out, N);
}

// round 9
// speedup vs baseline: 1.8192x; 1.0465x over previous
#include <cuda_runtime.h>
#include <mma.h>
#include <math.h>

using namespace nvcuda;

#define NN 50000
#define EE 600000
#define SCAN_B 256

// ------------------------- device scratch (no allocs allowed) ---------------
__device__ int   g_is64;
__device__ int   g_col[EE];          // src ids sorted by dst (CSR)
__device__ int   g_deg[NN + 1];
__device__ int   g_off[NN + 1];
__device__ int   g_pos[NN];
__device__ int   g_bsum[SCAN_B];
__device__ float g_hp [NN * 128];
__device__ float g_h  [NN * 128];
__device__ float g_as [NN * 4];
__device__ float g_ad [NN * 4];

// ------------------------- helpers ------------------------------------------
__device__ __forceinline__ float lrelu(float x) { return x > 0.f ? x : 0.2f * x; }

// ------------------------- edge index dtype probe ----------------------------
__global__ void probe_kernel(const unsigned long long* __restrict__ p) {
    if (threadIdx.x == 0 && blockIdx.x == 0) {
        int ok = 1;
        #pragma unroll
        for (int i = 0; i < 16; ++i)
            if (p[i] >= (unsigned long long)NN) ok = 0;
        g_is64 = ok;
    }
}

// histogram straight off the input edge list (no convert pass)
__global__ void hist_kernel(const void* __restrict__ ei, int E) {
    int e = blockIdx.x * blockDim.x + threadIdx.x;
    if (e >= E) return;
    int d = g_is64 ? (int)((const long long*)ei)[E + e]
                   : ((const int*)ei)[E + e];
    atomicAdd(&g_deg[d], 1);
}

// ------------------------- CSR build: 3-stage multi-block scan ---------------
__global__ __launch_bounds__(SCAN_B) void scanA_kernel(int N) {
    __shared__ int sm[SCAN_B];
    int i = blockIdx.x * SCAN_B + threadIdx.x;
    int t = threadIdx.x;
    sm[t] = (i < N) ? g_deg[i] : 0;
    __syncthreads();
    #pragma unroll
    for (int o = SCAN_B / 2; o > 0; o >>= 1) {
        if (t < o) sm[t] += sm[t + o];
        __syncthreads();
    }
    if (t == 0) g_bsum[blockIdx.x] = sm[0];
}

__global__ __launch_bounds__(SCAN_B) void scanB_kernel(int nb) {
    __shared__ int sm[SCAN_B];
    int t = threadIdx.x;
    int v = (t < nb) ? g_bsum[t] : 0;
    sm[t] = v;
    __syncthreads();
    #pragma unroll
    for (int o = 1; o < SCAN_B; o <<= 1) {
        int u = (t >= o) ? sm[t - o] : 0;
        __syncthreads();
        sm[t] += u;
        __syncthreads();
    }
    g_bsum[t] = sm[t] - v;     // exclusive
}

__global__ __launch_bounds__(SCAN_B) void scanC_kernel(int N) {
    __shared__ int sm[SCAN_B];
    int i = blockIdx.x * SCAN_B + threadIdx.x;
    int t = threadIdx.x;
    int v = (i < N) ? g_deg[i] : 0;
    sm[t] = v;
    __syncthreads();
    #pragma unroll
    for (int o = 1; o < SCAN_B; o <<= 1) {
        int u = (t >= o) ? sm[t - o] : 0;
        __syncthreads();
        sm[t] += u;
        __syncthreads();
    }
    int excl = sm[t] - v + g_bsum[blockIdx.x];
    if (i < N) { g_off[i] = excl; g_pos[i] = excl; }
    if (i == N - 1) g_off[N] = excl + v;
}

// scatter straight off the input edge list
__global__ void scatter_kernel(const void* __restrict__ ei, int E) {
    int e = blockIdx.x * blockDim.x + threadIdx.x;
    if (e >= E) return;
    int s, d;
    if (g_is64) {
        const long long* p = (const long long*)ei;
        s = (int)p[e]; d = (int)p[E + e];
    } else {
        const int* p = (const int*)ei;
        s = p[e]; d = p[E + e];
    }
    int pos = atomicAdd(&g_pos[d], 1);
    g_col[pos] = s;
}

// ------------------------- GEMM N x 128 @ 128 x 128 (tf32 WMMA) --------------
__global__ __launch_bounds__(256) void gemm128_tf32_kernel(
    const float* __restrict__ A, const float* __restrict__ W,
    float* __restrict__ C,
    const float* __restrict__ att_s, const float* __restrict__ att_d,
    float* __restrict__ as_out, float* __restrict__ ad_out, int N)
{
    extern __shared__ float sm[];
    float* Ws = sm;            // 128*128 (64KB)
    float* Xs = sm + 16384;    // 64*128  (32KB)
    int tid  = threadIdx.x;
    int row0 = blockIdx.x * 64;

    const float4* Wv  = (const float4*)W;
    float4*       Wsv = (float4*)Ws;
    #pragma unroll 4
    for (int i = tid; i < 4096; i += 256) Wsv[i] = Wv[i];

    const float4* Av  = (const float4*)A;
    float4*       Xsv = (float4*)Xs;
    #pragma unroll 2
    for (int i = tid; i < 2048; i += 256) {
        int r = i >> 5;
        int gr = row0 + r;
        Xsv[i] = (gr < N) ? Av[gr * 32 + (i & 31)] : make_float4(0.f, 0.f, 0.f, 0.f);
    }
    __syncthreads();

    int warp = tid >> 5;
    int wr = warp >> 2;
    int wc = warp & 3;

    wmma::fragment<wmma::accumulator, 16, 16, 8, float> cf[2][2];
    #pragma unroll
    for (int i = 0; i < 2; ++i)
        #pragma unroll
        for (int j = 0; j < 2; ++j) wmma::fill_fragment(cf[i][j], 0.f);

    #pragma unroll
    for (int k = 0; k < 128; k += 8) {
        wmma::fragment<wmma::matrix_a, 16, 16, 8, wmma::precision::tf32, wmma::row_major> af[2];
        wmma::fragment<wmma::matrix_b, 16, 16, 8, wmma::precision::tf32, wmma::row_major> bf[2];
        #pragma unroll
        for (int i = 0; i < 2; ++i) {
            wmma::load_matrix_sync(af[i], Xs + (wr * 32 + i * 16) * 128 + k, 128);
            #pragma unroll
            for (int t = 0; t < af[i].num_elements; ++t)
                af[i].x[t] = wmma::__float_to_tf32(af[i].x[t]);
        }
        #pragma unroll
        for (int j = 0; j < 2; ++j) {
            wmma::load_matrix_sync(bf[j], Ws + k * 128 + wc * 32 + j * 16, 128);
            #pragma unroll
            for (int t = 0; t < bf[j].num_elements; ++t)
                bf[j].x[t] = wmma::__float_to_tf32(bf[j].x[t]);
        }
        #pragma unroll
        for (int i = 0; i < 2; ++i)
            #pragma unroll
            for (int j = 0; j < 2; ++j)
                wmma::mma_sync(cf[i][j], af[i], bf[j], cf[i][j]);
    }

    __syncthreads();                     // done reading Ws; reuse as C stage
    float* Cs = Ws;                      // 64*128
    #pragma unroll
    for (int i = 0; i < 2; ++i)
        #pragma unroll
        for (int j = 0; j < 2; ++j)
            wmma::store_matrix_sync(Cs + (wr * 32 + i * 16) * 128 + wc * 32 + j * 16,
                                    cf[i][j], 128, wmma::mem_row_major);
    __syncthreads();

    const float4* Csv = (const float4*)Cs;
    #pragma unroll 2
    for (int i = tid; i < 2048; i += 256) {
        int r = i >> 5;
        int gr = row0 + r;
        if (gr < N) ((float4*)C)[gr * 32 + (i & 31)] = Csv[i];
    }
    // fused attention scores: thread -> (row, head)
    {
        int r = tid >> 2, h = tid & 3;
        int gr = row0 + r;
        if (gr < N) {
            const float* cp = Cs + r * 128 + h * 32;
            float s = 0.f, d = 0.f;
            #pragma unroll
            for (int j = 0; j < 32; ++j) {
                float v = cp[j];
                s += v * __ldg(att_s + h * 32 + j);
                d += v * __ldg(att_d + h * 32 + j);
            }
            as_out[gr * 4 + h] = s;
            ad_out[gr * 4 + h] = d;
        }
    }
}

// ------------------------- fused CSR aggregation, H=4, D=32 ------------------
// one warp per dst node, split into two 16-lane groups processing 2 edges per
// iteration (lane q owns floats [8q,8q+8), head h=q>>2). atomic-free; halves
// the serial trip count and doubles memory-level parallelism.
__global__ __launch_bounds__(256) void agg4_kernel(
    const float* __restrict__ bias, const float* __restrict__ gamma,
    const float* __restrict__ beta, float* __restrict__ outp, int N)
{
    int w = (blockIdx.x * blockDim.x + threadIdx.x) >> 5;
    if (w >= N) return;
    int lane = threadIdx.x & 31;
    int grp  = lane >> 4;
    int q    = lane & 15;
    int h    = q >> 2;
    int f    = q * 8;
    int n = w;
    int beg = g_off[n], end = g_off[n + 1];

    float4 adn = *(const float4*)(g_ad + n * 4);
    float4 asn = *(const float4*)(g_as + n * 4);
    float4 sl4 = make_float4(lrelu(asn.x + adn.x), lrelu(asn.y + adn.y),
                             lrelu(asn.z + adn.z), lrelu(asn.w + adn.w));
    // ---- phase 1: per-head segment max, strided over all 32 lanes ----
    float4 mx = sl4;
    for (int e = beg + lane; e < end; e += 32) {
        int s = g_col[e];
        float4 a = *(const float4*)(g_as + s * 4);
        mx.x = fmaxf(mx.x, lrelu(a.x + adn.x));
        mx.y = fmaxf(mx.y, lrelu(a.y + adn.y));
        mx.z = fmaxf(mx.z, lrelu(a.z + adn.z));
        mx.w = fmaxf(mx.w, lrelu(a.w + adn.w));
    }
    #pragma unroll
    for (int o = 16; o > 0; o >>= 1) {
        mx.x = fmaxf(mx.x, __shfl_xor_sync(0xffffffffu, mx.x, o));
        mx.y = fmaxf(mx.y, __shfl_xor_sync(0xffffffffu, mx.y, o));
        mx.z = fmaxf(mx.z, __shfl_xor_sync(0xffffffffu, mx.z, o));
        mx.w = fmaxf(mx.w, __shfl_xor_sync(0xffffffffu, mx.w, o));
    }
    float mxh  = (h == 0) ? mx.x  : (h == 1) ? mx.y  : (h == 2) ? mx.z  : mx.w;
    float adnh = (h == 0) ? adn.x : (h == 1) ? adn.y : (h == 2) ? adn.z : adn.w;
    float slh  = (h == 0) ? sl4.x : (h == 1) ? sl4.y : (h == 2) ? sl4.z : sl4.w;

    // ---- phase 2: group 0 seeds the self-loop; 2 edges per iteration ----
    float4 a0 = make_float4(0.f, 0.f, 0.f, 0.f);
    float4 a1 = make_float4(0.f, 0.f, 0.f, 0.f);
    float den = 0.f;
    if (grp == 0) {
        float exs = __expf(slh - mxh);
        const float4* hv = (const float4*)(g_hp + (size_t)n * 128 + f);
        float4 v0 = hv[0], v1 = hv[1];
        a0 = make_float4(exs * v0.x, exs * v0.y, exs * v0.z, exs * v0.w);
        a1 = make_float4(exs * v1.x, exs * v1.y, exs * v1.z, exs * v1.w);
        den = exs;
    }
    for (int e = beg; e < end; e += 2) {
        int ee = e + grp;
        if (ee < end) {
            int s = g_col[ee];
            float ex = __expf(lrelu(__ldg(g_as + s * 4 + h) + adnh) - mxh);
            den += ex;
            const float4* vp = (const float4*)(g_hp + (size_t)s * 128 + f);
            float4 v0 = vp[0], v1 = vp[1];
            a0.x += ex * v0.x; a0.y += ex * v0.y; a0.z += ex * v0.z; a0.w += ex * v0.w;
            a1.x += ex * v1.x; a1.y += ex * v1.y; a1.z += ex * v1.z; a1.w += ex * v1.w;
        }
    }
    // combine the two groups (matching q across halves -> same head)
    den  += __shfl_xor_sync(0xffffffffu, den,  16);
    a0.x += __shfl_xor_sync(0xffffffffu, a0.x, 16);
    a0.y += __shfl_xor_sync(0xffffffffu, a0.y, 16);
    a0.z += __shfl_xor_sync(0xffffffffu, a0.z, 16);
    a0.w += __shfl_xor_sync(0xffffffffu, a0.w, 16);
    a1.x += __shfl_xor_sync(0xffffffffu, a1.x, 16);
    a1.y += __shfl_xor_sync(0xffffffffu, a1.y, 16);
    a1.z += __shfl_xor_sync(0xffffffffu, a1.z, 16);
    a1.w += __shfl_xor_sync(0xffffffffu, a1.w, 16);

    if (grp == 0) {
        float inv = 1.f / (den + 1e-16f);
        const float bns = rsqrtf(1.f + 1e-5f);
        float4 bi0 = *(const float4*)(bias  + f), bi1 = *(const float4*)(bias  + f + 4);
        float4 ga0 = *(const float4*)(gamma + f), ga1 = *(const float4*)(gamma + f + 4);
        float4 be0 = *(const float4*)(beta  + f), be1 = *(const float4*)(beta  + f + 4);
        float4 o0, o1;
        o0.x = a0.x * inv + bi0.x; o0.x = o0.x * (ga0.x * bns) + be0.x; o0.x = o0.x > 0.f ? o0.x : expm1f(o0.x);
        o0.y = a0.y * inv + bi0.y; o0.y = o0.y * (ga0.y * bns) + be0.y; o0.y = o0.y > 0.f ? o0.y : expm1f(o0.y);
        o0.z = a0.z * inv + bi0.z; o0.z = o0.z * (ga0.z * bns) + be0.z; o0.z = o0.z > 0.f ? o0.z : expm1f(o0.z);
        o0.w = a0.w * inv + bi0.w; o0.w = o0.w * (ga0.w * bns) + be0.w; o0.w = o0.w > 0.f ? o0.w : expm1f(o0.w);
        o1.x = a1.x * inv + bi1.x; o1.x = o1.x * (ga1.x * bns) + be1.x; o1.x = o1.x > 0.f ? o1.x : expm1f(o1.x);
        o1.y = a1.y * inv + bi1.y; o1.y = o1.y * (ga1.y * bns) + be1.y; o1.y = o1.y > 0.f ? o1.y : expm1f(o1.y);
        o1.z = a1.z * inv + bi1.z; o1.z = o1.z * (ga1.z * bns) + be1.z; o1.z = o1.z > 0.f ? o1.z : expm1f(o1.z);
        o1.w = a1.w * inv + bi1.w; o1.w = o1.w * (ga1.w * bns) + be1.w; o1.w = o1.w > 0.f ? o1.w : expm1f(o1.w);
        float4* op = (float4*)(outp + (size_t)n * 128 + f);
        op[0] = o0; op[1] = o1;
    }
}

// ------------------------- layer 3 (H=1, D=CLS=10) ---------------------------
// scores for layer 2 fused into the GEMM epilogue.
__global__ __launch_bounds__(320) void gemm10_kernel(
    const float* __restrict__ A, const float* __restrict__ W,
    float* __restrict__ C,
    const float* __restrict__ as2, const float* __restrict__ ad2, int N)
{
    __shared__ float Xs[32 * 128];
    __shared__ float Ws[128 * 10];
    __shared__ float Cs[32 * 10];
    int tid  = threadIdx.x;
    int row0 = blockIdx.x * 32;
    for (int i = tid; i < 1280; i += 320) Ws[i] = W[i];
    for (int i = tid; i < 1024; i += 320) {
        int r = i >> 5;
        int gr = row0 + r;
        float4 v = make_float4(0.f, 0.f, 0.f, 0.f);
        if (gr < N) v = ((const float4*)A)[gr * 32 + (i & 31)];
        ((float4*)Xs)[i] = v;
    }
    __syncthreads();
    int r = tid / 10, c = tid - r * 10;
    if (r < 32) {
        int row = row0 + r;
        float s = 0.f;
        #pragma unroll 8
        for (int k = 0; k < 128; ++k) s += Xs[r * 128 + k] * Ws[k * 10 + c];
        Cs[r * 10 + c] = s;
        if (row < N) C[row * 10 + c] = s;
    }
    __syncthreads();
    if (tid < 32) {
        int row = row0 + tid;
        if (row < N) {
            float s = 0.f, d = 0.f;
            #pragma unroll
            for (int cc = 0; cc < 10; ++cc) {
                float v = Cs[tid * 10 + cc];
                s += v * __ldg(as2 + cc);
                d += v * __ldg(ad2 + cc);
            }
            g_as[row] = s;
            g_ad[row] = d;
        }
    }
}

// fused CSR aggregation for layer 2 (H=1, D=10); 2 edges per iteration.
__global__ __launch_bounds__(256) void agg1_kernel(
    const float* __restrict__ b2, float* __restrict__ out, int N)
{
    int w = (blockIdx.x * blockDim.x + threadIdx.x) >> 5;
    if (w >= N) return;
    int lane = threadIdx.x & 31;
    int grp  = lane >> 4;
    int sub  = lane & 15;
    int n = w;
    int beg = g_off[n], end = g_off[n + 1];
    float adn = g_ad[n];
    float sl  = lrelu(g_as[n] + adn);
    float mx  = sl;
    for (int e = beg + lane; e < end; e += 32)
        mx = fmaxf(mx, lrelu(g_as[g_col[e]] + adn));
    #pragma unroll
    for (int o = 16; o > 0; o >>= 1)
        mx = fmaxf(mx, __shfl_xor_sync(0xffffffffu, mx, o));

    float den = 0.f, acc = 0.f;
    if (grp == 0) {
        float exs = __expf(sl - mx);
        den = exs;
        if (sub < 10) acc = exs * g_hp[(size_t)n * 10 + sub];
    }
    for (int e = beg; e < end; e += 2) {
        int ee = e + grp;
        if (ee < end) {
            int s = g_col[ee];
            float ex = __expf(lrelu(__ldg(g_as + s) + adn) - mx);
            den += ex;
            if (sub < 10) acc += ex * __ldg(g_hp + (size_t)s * 10 + sub);
        }
    }
    den += __shfl_xor_sync(0xffffffffu, den, 16);
    acc += __shfl_xor_sync(0xffffffffu, acc, 16);
    if (grp == 0 && sub < 10)
        out[(size_t)n * 10 + sub] = acc / (den + 1e-16f) + __ldg(b2 + sub);
}

// ------------------------- host launch ---------------------------------------
extern "C" void kernel_launch(void* const* d_in, const int* in_sizes, int n_in,
                              void* d_out, int out_size)
{
    const float* x   = (const float*)d_in[0];
    const void*  ei  = d_in[1];
    const float* W0  = (const float*)d_in[2];
    const float* as0 = (const float*)d_in[3];
    const float* ad0 = (const float*)d_in[4];
    const float* b0  = (const float*)d_in[5];
    const float* g0  = (const float*)d_in[6];
    const float* be0 = (const float*)d_in[7];
    const float* W1  = (const float*)d_in[8];
    const float* as1 = (const float*)d_in[9];
    const float* ad1 = (const float*)d_in[10];
    const float* b1  = (const float*)d_in[11];
    const float* g1  = (const float*)d_in[12];
    const float* be1 = (const float*)d_in[13];
    const float* W2  = (const float*)d_in[14];
    const float* as2 = (const float*)d_in[15];
    const float* ad2 = (const float*)d_in[16];
    const float* b2  = (const float*)d_in[17];
    float* out = (float*)d_out;

    int N = in_sizes[0] / 128;
    int E = in_sizes[1] / 2;
    if (N > NN) N = NN;
    if (E > EE) E = EE;

    cudaFuncSetAttribute(gemm128_tf32_kernel,
                         cudaFuncAttributeMaxDynamicSharedMemorySize, 98304);

    float* hp_dev;  cudaGetSymbolAddress((void**)&hp_dev,  g_hp);
    float* h_dev;   cudaGetSymbolAddress((void**)&h_dev,   g_h);
    float* as_dev;  cudaGetSymbolAddress((void**)&as_dev,  g_as);
    float* ad_dev;  cudaGetSymbolAddress((void**)&ad_dev,  g_ad);
    int*   deg_dev; cudaGetSymbolAddress((void**)&deg_dev, g_deg);

    // one-time side stream + fork/join events (created outside graph capture:
    // the harness's first call is the un-captured correctness run)
    static cudaStream_t s2 = nullptr;
    static cudaEvent_t evF = nullptr, evJ = nullptr;
    if (s2 == nullptr) {
        cudaStreamCreateWithFlags(&s2, cudaStreamNonBlocking);
        cudaEventCreateWithFlags(&evF, cudaEventDisableTiming);
        cudaEventCreateWithFlags(&evJ, cudaEventDisableTiming);
    }

    dim3 b256(256);
    int gbEdge = (E + 255) / 256;
    int gbG    = (N + 63) / 64;
    int gbWarp = (N * 32 + 255) / 256;   // one warp per node
    int nScanB = (N + SCAN_B - 1) / SCAN_B;

    // ---- fork: CSR build on side stream, overlapped with layer-0 GEMM ----
    cudaEventRecord(evF, 0);
    cudaStreamWaitEvent(s2, evF, 0);
    probe_kernel<<<1, 32, 0, s2>>>((const unsigned long long*)ei);
    cudaMemsetAsync(deg_dev, 0, (NN + 1) * sizeof(int), s2);
    hist_kernel<<<gbEdge, b256, 0, s2>>>(ei, E);
    scanA_kernel<<<nScanB, SCAN_B, 0, s2>>>(N);
    scanB_kernel<<<1, SCAN_B, 0, s2>>>(nScanB);
    scanC_kernel<<<nScanB, SCAN_B, 0, s2>>>(N);
    scatter_kernel<<<gbEdge, b256, 0, s2>>>(ei, E);
    cudaEventRecord(evJ, s2);

    // ---- layer 0 GEMM on main stream (independent of CSR) ----
    gemm128_tf32_kernel<<<gbG, b256, 98304>>>(x, W0, hp_dev, as0, ad0, as_dev, ad_dev, N);
    cudaStreamWaitEvent(0, evJ, 0);      // join before aggregation
    agg4_kernel<<<gbWarp, b256>>>(b0, g0, be0, h_dev, N);

    // ---- layer 1 ----
    gemm128_tf32_kernel<<<gbG, b256, 98304>>>(h_dev, W1, hp_dev, as1, ad1, as_dev, ad_dev, N);
    agg4_kernel<<<gbWarp, b256>>>(b1, g1, be1, h_dev, N);

    // ---- layer 2 (H=1, D=10) ----
    gemm10_kernel<<<(N + 31) / 32, 320>>>(h_dev, W2, hp_dev, as2, ad2, N);
    agg1_kernel<<<gbWarp, b256>>>(b2, out, N);
}